// round 6
// baseline (speedup 1.0000x reference)
#include <cuda_runtime.h>
#include <math.h>

#define TWO_PI_F 6.28318530717958647692f

// ---------------------------------------------------------------------------
// Per-point dltar4: serial Haskell-matrix recursion over L layers.
// Layer data (d, b, 1/a, 1/b, rho, 1/rho) lives in shared memory.
// ---------------------------------------------------------------------------
__device__ __forceinline__ float dltar4_point(
    float wvno, float omega, float inv_omega, int L,
    const float* __restrict__ sd, const float* __restrict__ sbv,
    const float* __restrict__ sia, const float* __restrict__ sib,
    const float* __restrict__ srho, const float* __restrict__ sirho)
{
    const float wvno2 = wvno * wvno;
    float e0, e1, e2, e3, e4;

    // Halfspace (layer L-1) initialization
    {
        float xka   = omega * sia[L - 1];
        float xkb   = omega * sib[L - 1];
        float ra    = sqrtf(fabsf(wvno2 - xka * xka));
        float rb    = sqrtf(fabsf(wvno2 - xkb * xkb));
        float t     = sbv[L - 1] * inv_omega;
        float gammk = 2.0f * t * t;
        float gam   = gammk * wvno2;
        float gamm1 = gam - 1.0f;
        float r     = srho[L - 1];
        float rarb  = ra * rb;
        e0 = r * r * (gamm1 * gamm1 - gam * gammk * rarb);
        e1 = -r * ra;
        e2 = r * (gamm1 - gammk * rarb);
        e3 = r * rb;
        e4 = wvno2 - rarb;
    }

#pragma unroll 1
    for (int il = L - 2; il >= 0; --il) {
        const float dm  = sd[il];
        const float bm  = sbv[il];
        const float xka = omega * sia[il];
        const float xkb = omega * sib[il];
        const float t   = bm * inv_omega;
        const float gammk = 2.0f * t * t;
        const float gam   = gammk * wvno2;
        const float ra = sqrtf(fabsf(wvno2 - xka * xka));
        const float rb = sqrtf(fabsf(wvno2 - xkb * xkb));
        const float p  = ra * dm;
        const float q  = rb * dm;

        // ---- _var ----
        float pex, cosp, w, x;
        {
            const bool lt = wvno < xka;
            const bool gt = wvno > xka;
            float sinp, cf;
            __sincosf(p, &sinp, &cf);
            const float fac = (p < 16.0f) ? __expf(-2.0f * p) : 0.0f;
            const float ce  = (1.0f + fac) * 0.5f;
            const float se  = (1.0f - fac) * 0.5f;
            const float ras = (ra > 0.0f) ? ra : 1.0f;
            pex  = gt ? p : 0.0f;
            cosp = lt ? cf : (gt ? ce : 1.0f);
            w    = lt ? __fdividef(sinp, ras) : (gt ? __fdividef(se, ras) : dm);
            x    = lt ? (-ra * sinp) : (gt ? (ra * se) : 0.0f);
        }
        float sex, cosq, y, z;
        {
            const bool lt = wvno < xkb;
            const bool gt = wvno > xkb;
            float sinq, cf;
            __sincosf(q, &sinq, &cf);
            const float fac = (q < 16.0f) ? __expf(-2.0f * q) : 0.0f;
            const float ce  = (1.0f + fac) * 0.5f;
            const float se  = (1.0f - fac) * 0.5f;
            const float rbs = (rb > 0.0f) ? rb : 1.0f;
            sex  = gt ? q : 0.0f;
            cosq = lt ? cf : (gt ? ce : 1.0f);
            y    = lt ? __fdividef(sinq, rbs) : (gt ? __fdividef(se, rbs) : dm);
            z    = lt ? (-rb * sinq) : (gt ? (rb * se) : 0.0f);
        }
        const float exa = pex + sex;
        const float a0  = (exa < 60.0f) ? __expf(-exa) : 0.0f;

        const float cpcq = cosp * cosq;
        const float cpy  = cosp * y;
        const float cpz  = cosp * z;
        const float cqw  = cosq * w;
        const float cqx  = cosq * x;
        const float xy   = x * y;
        const float xz   = x * z;
        const float wy   = w * y;
        const float wz   = w * z;

        // ---- _dnka ----
        const float gamm1 = gam - 1.0f;
        const float twgm1 = gam + gamm1;
        const float gmgmk = gam * gammk;
        const float gmgm1 = gam * gamm1;
        const float gm1sq = gamm1 * gamm1;
        const float rho   = srho[il];
        const float irho  = sirho[il];
        const float rho2  = rho * rho;
        const float irho2 = irho * irho;
        const float a0pq  = a0 - cpcq;
        const float tt    = -2.0f * wvno2;

        const float c00 = cpcq - 2.0f * gmgm1 * a0pq - gmgmk * xz - wvno2 * gm1sq * wy;
        const float c01 = (wvno2 * cpy - cqx) * irho;
        const float c02 = -(twgm1 * a0pq + gammk * xz + wvno2 * gamm1 * wy) * irho;
        const float c03 = (cpz - wvno2 * cqw) * irho;
        const float c04 = -(2.0f * wvno2 * a0pq + xz + wvno2 * wvno2 * wy) * irho2;
        const float c10 = (gmgmk * cpz - gm1sq * cqw) * rho;
        const float c11 = cpcq;
        const float c12 = gammk * cpz - gamm1 * cqw;
        const float c13 = -wz;
        const float c30 = (gm1sq * cpy - gmgmk * cqx) * rho;
        const float c31 = -xy;
        const float c32 = gamm1 * cpy - gammk * cqx;
        const float c40 = -(2.0f * gmgmk * gm1sq * a0pq + gmgmk * gmgmk * xz
                            + gm1sq * gm1sq * wy) * rho2;
        const float c42 = -(gammk * gamm1 * twgm1 * a0pq + gam * gammk * gammk * xz
                            + gamm1 * gm1sq * wy) * rho;
        const float c20 = tt * c42;
        const float c21 = tt * c32;
        const float c22 = a0 + 2.0f * (cpcq - c00);
        const float c23 = tt * c12;
        const float c24 = tt * c02;

        // ee_i = sum_j e_j * ca[j][i]
        const float ee0 = e0 * c00 + e1 * c10 + e2 * c20 + e3 * c30 + e4 * c40;
        const float ee1 = e0 * c01 + e1 * c11 + e2 * c21 + e3 * c31 + e4 * c30;
        const float ee2 = e0 * c02 + e1 * c12 + e2 * c22 + e3 * c32 + e4 * c42;
        const float ee3 = e0 * c03 + e1 * c13 + e2 * c23 + e3 * c11 + e4 * c10;
        const float ee4 = e0 * c04 + e1 * c03 + e2 * c24 + e3 * c01 + e4 * c00;

        float t1 = fmaxf(fabsf(ee0),
                   fmaxf(fabsf(ee1),
                   fmaxf(fabsf(ee2),
                   fmaxf(fabsf(ee3), fabsf(ee4)))));
        if (t1 < 1e-30f) t1 = 1.0f;
        const float s = __fdividef(1.0f, t1);
        e0 = ee0 * s; e1 = ee1 * s; e2 = ee2 * s; e3 = ee3 * s; e4 = ee4 * s;
    }
    return e0;
}

// ---------------------------------------------------------------------------
// Main kernel: one block per (m, p). 128 threads stride over 401 work items:
// items 0..NC-1 are the C-grid dets (for rng = max - min), item NC is the
// e00 det at wvno = omega / vlist[m,p].
// ---------------------------------------------------------------------------
__global__ void __launch_bounds__(128)
forward_kernel(const float* __restrict__ vlist, const float* __restrict__ tlist,
               const float* __restrict__ dlay, const float* __restrict__ blay,
               const float* __restrict__ Clist, float* __restrict__ out,
               int M, int P, int L, int NC)
{
    __shared__ float sC[1024];
    __shared__ float sd[64], sbv[64], sia[64], sib[64], srho[64], sirho[64];
    __shared__ float red_mn[4], red_mx[4], sh_e00;

    const int m   = blockIdx.y;
    const int p   = blockIdx.x;
    const int tid = threadIdx.x;

    for (int l = tid; l < L; l += blockDim.x) {
        const float bv = blay[m * L + l];
        // a = 0.9409 + 2.0947 b - 0.8206 b^2 + 0.2683 b^3 - 0.0251 b^4
        const float av = 0.9409f + bv * (2.0947f + bv * (-0.8206f + bv * (0.2683f + bv * (-0.0251f))));
        // rho = 1.6612 a - 0.4721 a^2 + 0.0671 a^3 - 0.0043 a^4 + 0.000106 a^5
        const float rv = av * (1.6612f + av * (-0.4721f + av * (0.0671f + av * (-0.0043f + av * 0.000106f))));
        sd[l]    = dlay[m * L + l];
        sbv[l]   = bv;
        sia[l]   = 1.0f / av;
        sib[l]   = 1.0f / bv;
        srho[l]  = rv;
        sirho[l] = 1.0f / rv;
    }
    for (int k = tid; k < NC; k += blockDim.x) sC[k] = Clist[k];
    __syncthreads();

    float om = TWO_PI_F / tlist[m * P + p];
    om = fmaxf(om, 1e-4f);
    const float iom = 1.0f / om;

    float mn =  3.4e38f;
    float mx = -3.4e38f;

    for (int k = tid; k <= NC; k += blockDim.x) {
        const float wv = (k < NC) ? (om / sC[k]) : (om / vlist[m * P + p]);
        const float det = dltar4_point(wv, om, iom, L, sd, sbv, sia, sib, srho, sirho);
        if (k < NC) {
            mn = fminf(mn, det);
            mx = fmaxf(mx, det);
        } else {
            sh_e00 = det;
        }
    }

    // Block reduction of min/max over the NC grid dets
    const unsigned full = 0xffffffffu;
#pragma unroll
    for (int o = 16; o > 0; o >>= 1) {
        mn = fminf(mn, __shfl_xor_sync(full, mn, o));
        mx = fmaxf(mx, __shfl_xor_sync(full, mx, o));
    }
    if ((tid & 31) == 0) {
        red_mn[tid >> 5] = mn;
        red_mx[tid >> 5] = mx;
    }
    __syncthreads();

    if (tid == 0) {
        mn = fminf(fminf(red_mn[0], red_mn[1]), fminf(red_mn[2], red_mn[3]));
        mx = fmaxf(fmaxf(red_mx[0], red_mx[1]), fmaxf(red_mx[2], red_mx[3]));
        const float rng = mx - mn;
        const float val = sh_e00 / rng;
        // |0.1^|val| - 1| = 1 - 10^(-|val|)
        const float contrib = (1.0f - exp10f(-fabsf(val))) / (float)P;
        atomicAdd(&out[m], contrib);
    }
}

// ---------------------------------------------------------------------------
// Regularizer: out[m] += sum_i |(Lmat_v @ b[m])_i| / L   (DAMP_HORIZONTAL = 0)
// ---------------------------------------------------------------------------
__global__ void reg_kernel(const float* __restrict__ blay, float* __restrict__ out,
                           int M, int L)
{
    const int m = blockIdx.x * blockDim.x + threadIdx.x;
    if (m >= M) return;
    const float* bm = blay + m * L;
    float s = 0.0f;
    for (int i = 0; i < L; ++i) {
        float v;
        if (i == 0)            v = bm[0] - bm[1];
        else if (i == L - 1)   v = bm[L - 1] - bm[L - 2];
        else                   v = 2.0f * bm[i] - bm[i - 1] - bm[i + 1];
        s += fabsf(v);
    }
    out[m] += s / (float)L;
}

extern "C" void kernel_launch(void* const* d_in, const int* in_sizes, int n_in,
                              void* d_out, int out_size)
{
    const float* vlist = (const float*)d_in[0];
    const float* tlist = (const float*)d_in[1];
    const float* dlay  = (const float*)d_in[2];
    const float* blay  = (const float*)d_in[3];
    const float* Clist = (const float*)d_in[4];
    float* out = (float*)d_out;

    const int M  = out_size;              // 64
    const int P  = in_sizes[0] / M;       // 100
    const int L  = in_sizes[3] / M;       // 32
    const int NC = in_sizes[4];           // 400

    cudaMemsetAsync(out, 0, (size_t)M * sizeof(float));

    dim3 grid(P, M);
    forward_kernel<<<grid, 128>>>(vlist, tlist, dlay, blay, Clist, out, M, P, L, NC);

    reg_kernel<<<1, M>>>(blay, out, M, L);
}